// round 11
// baseline (speedup 1.0000x reference)
#include <cuda_runtime.h>
#include <cstdint>

// CTC prefix beam search — bit-exact vs JAX reference.
// One warp per batch element; all state in registers + shfl.
// R11: sorting network moved to (float score, u32 payload) pairs so the
//      compare-exchanges run on the FMA pipe (FSETP/FSEL) instead of the
//      saturated ALU pipe. Ordering identical to u64 (ord(s)<<32|p) compare.

#define BATCH 1024
#define TT    128
#define CCC   63
#define VVV   62
#define WW    8
#define NEGF  (-1e30f)
#define HB1C  1000003u
#define HB2C  2654435761u
#define WPB   4
#define FULL  0xffffffffu

typedef unsigned long long u64;
typedef unsigned int u32;

__device__ __forceinline__ float lax_logaddexp(float a, float b) {
    float m = fmaxf(a, b);
    return m + log1pf(expf(-fabsf(a - b)));
}
__device__ __forceinline__ float seg_lse2(float a, float b) {
    float m = fmaxf(a, b);
    float s = expf(a - m) + expf(b - m);
    return logf(fmaxf(s, 1e-30f)) + m;
}
__device__ __forceinline__ u32 ord_of_float(float f) {
    u32 u = __float_as_uint(f);
    return (u & 0x80000000u) ? ~u : (u | 0x80000000u);
}
__device__ __forceinline__ float float_of_ord(u32 u) {
    return __uint_as_float((u & 0x80000000u) ? (u & 0x7fffffffu) : ~u);
}

// lexicographic (score, payload) compare-exchange — identical order to the
// u64 (ord(score)<<32 | payload) compare. FSETP/FSEL -> fma pipe.
__device__ __forceinline__ void cexf(float& sa, u32& pa, float& sb, u32& pb) {
    bool q = (sa > sb) || (sa == sb && pa > pb);
    float ts = q ? sa : sb;
    float us = q ? sb : sa;
    u32   tp = q ? pa : pb;
    u32   up = q ? pb : pa;
    sa = ts; sb = us; pa = tp; pb = up;
}
__device__ __forceinline__ void kmaxf(float& sa, u32& pa, float sb, u32 pb) {
    bool q = (sa > sb) || (sa == sb && pa > pb);
    sa = q ? sa : sb;
    pa = q ? pa : pb;
}

#define CEXK(i, j) cexf(S[i], P[i], S[j], P[j])
#define CEXT(i, j) cexf(TS[i], TP[i], TS[j], TP[j])
// Batcher 19-CE sort (desc) of 8 pairs
#define SORT8P(O)                                                        \
    do {                                                                 \
        CEXK(O+0,O+1); CEXK(O+2,O+3); CEXK(O+4,O+5); CEXK(O+6,O+7);      \
        CEXK(O+0,O+2); CEXK(O+1,O+3); CEXK(O+4,O+6); CEXK(O+5,O+7);      \
        CEXK(O+1,O+2); CEXK(O+5,O+6);                                    \
        CEXK(O+0,O+4); CEXK(O+1,O+5); CEXK(O+2,O+6); CEXK(O+3,O+7);      \
        CEXK(O+2,O+4); CEXK(O+3,O+5);                                    \
        CEXK(O+1,O+2); CEXK(O+3,O+4); CEXK(O+5,O+6);                     \
    } while (0)
// bitonic merge (desc) of a bitonic 8-seq of pairs -> sorted desc
#define BMERGE8P()                                                       \
    do {                                                                 \
        CEXT(0,4); CEXT(1,5); CEXT(2,6); CEXT(3,7);                      \
        CEXT(0,2); CEXT(1,3); CEXT(4,6); CEXT(5,7);                      \
        CEXT(0,1); CEXT(2,3); CEXT(4,5); CEXT(6,7);                      \
    } while (0)

__global__ void ctc_beam_kernel(const float* __restrict__ logits,
                                float* __restrict__ out) {
    __shared__ unsigned short hist[WPB][TT * WW];  // (parent<<8)|(char+1)
    const int wip  = threadIdx.x >> 5;
    const int lane = threadIdx.x & 31;
    const int b    = blockIdx.x * WPB + wip;
    const float* base = logits + (size_t)b * TT * CCC;
    const float NINF = __int_as_float(0xff800000);

    // beam state (valid on lanes 0..7; lane j == beam j)
    u32 bm_h1 = 1u, bm_h2 = 1u;
    float bm_pb  = (lane == 0) ? 0.0f : NEGF;
    float bm_pnb = NEGF;
    int bm_last = -1, bm_len = 0;
    float bm_spb = NEGF, bm_mpnb = NEGF;

    const u32 Mlow = ((u32)lane << 5) - ((u32)lane << 10);
    const u32 ordDeadThr = ord_of_float(0.5f * NEGF);

    // softmax frame 0
    float lp0, lp1;
    {
        float cx0 = base[lane];
        float cx1 = (lane < 31) ? base[lane + 32] : NINF;
        u32 mo = __reduce_max_sync(FULL, ord_of_float(fmaxf(cx0, cx1)));
        float mx = float_of_ord(mo);
        float e0 = expf(cx0 - mx);
        float e1 = (lane < 31) ? expf(cx1 - mx) : 0.0f;
        float sm = e0 + e1;
        #pragma unroll
        for (int off = 16; off; off >>= 1)
            sm += __shfl_xor_sync(FULL, sm, off);
        float lse = logf(sm);
        lp0 = cx0 - mx - lse;
        lp1 = cx1 - mx - lse;
    }
    // prefetch frame 1
    float nx0 = base[CCC + lane];
    float nx1 = (lane < 31) ? base[CCC + lane + 32] : NINF;

    // duplicates exist ONLY at t=0 (validated in R10, rel_err 0.0)
    u32 dupmask = 0xFEu;

    for (int t = 0; t < TT; ++t) {
        int dup = (int)((dupmask >> lane) & 1u);

        // ---- 2a: per-beam prep ----
        float lpBlank = __shfl_sync(FULL, lp1, 30);   // class 62
        int ls = (bm_last >= 0) ? (bm_last & 31) : 0;
        float v0 = __shfl_sync(FULL, lp0, ls);
        float v1 = __shfl_sync(FULL, lp1, ls);
        float lpLast = (bm_last >= 32) ? v1 : v0;

        float bm_ptot = lax_logaddexp(bm_pb, bm_pnb);
        bm_spb = bm_ptot + lpBlank;
        float bm_spnb = (bm_last >= 0) ? (bm_pnb + lpLast) : NEGF;

        // ---- 2b: inverted merge detection ----
        int msrc = -1;
        #pragma unroll
        for (int i = 0; i < WW; ++i) {
            u32 ih1 = __shfl_sync(FULL, bm_h1, i);
            u32 ih2 = __shfl_sync(FULL, bm_h2, i);
            u32 c1 = bm_h1 - ih1 * HB1C - 1u;
            if (!((dupmask >> i) & 1u) && c1 < (u32)VVV &&
                bm_h2 == ih2 * HB2C + c1 + 1u)
                msrc = i * 64 + (int)c1;
        }
        if (dup || lane >= WW) msrc = -1;

        // kill masks: bit i -> extend (beam i, class lane[/+32]) merged or dup
        u32 killLo = dupmask, killHi = dupmask;
        #pragma unroll
        for (int j = 0; j < WW; ++j) {
            int ms = __shfl_sync(FULL, msrc, j);
            if (ms >= 0) {
                int mi = ms >> 6, mc = ms & 63;
                if (mc == lane) killLo |= 1u << mi;
                if (mc == lane + 32) killHi |= 1u << mi;
            }
        }

        // ---- 3: extend keys as (float score, u32 payload) pairs ----
        float S[16];
        u32   P[16];
        #pragma unroll
        for (int i = 0; i < WW; ++i) {
            int   ilast = __shfl_sync(FULL, bm_last, i);
            float ipb   = __shfl_sync(FULL, bm_pb, i);
            float ipt   = __shfl_sync(FULL, bm_ptot, i);
            float sl = ((lane == ilast) ? ipb : ipt) + lp0;
            if ((killLo >> i) & 1u) sl = NEGF;
            S[i] = sl;
            P[i] = (u32)(((u32)(1015 - 62 * i) << 10) + (u32)i) + Mlow;
            float sh = ((lane + 32 == ilast) ? ipb : ipt) + lp1;
            if ((killHi >> i) & 1u) sh = NEGF;
            S[i + 8] = (lane < 30) ? sh : NINF;
            P[i + 8] = (u32)(((u32)(983 - 62 * i) << 10) + (u32)(i + 8)) + Mlow;
        }

        // local sort of extends: two sorted 8-lists -> bitonic-split top-8
        SORT8P(0);
        SORT8P(8);
        float TS[8];
        u32   TP[8];
        #pragma unroll
        for (int k = 0; k < 8; ++k) {
            TS[k] = S[k]; TP[k] = P[k];
            kmaxf(TS[k], TP[k], S[15 - k], P[15 - k]);
        }
        BMERGE8P();

        // merged stay pnb (MUFU chain; overlaps the sort issue above)
        {
            int mi = (msrc >= 0) ? (msrc >> 6) : 0;
            int mc = (msrc >= 0) ? (msrc & 63) : 0;
            float mpbv = __shfl_sync(FULL, bm_pb, mi);
            float mptv = __shfl_sync(FULL, bm_ptot, mi);
            int   mlv  = __shfl_sync(FULL, bm_last, mi);
            float w0 = __shfl_sync(FULL, lp0, mc & 31);
            float w1 = __shfl_sync(FULL, lp1, mc & 31);
            float lpc = (mc >= 32) ? w1 : w0;
            float bv = ((mc == mlv) ? mpbv : mptv) + lpc;
            bm_mpnb = (msrc >= 0) ? seg_lse2(bm_spnb, bv) : bm_spnb;
        }
        // stay candidate (slot 16, idx = lane): insert into sorted list
        float cs0 = dup ? NEGF : lax_logaddexp(bm_spb, bm_mpnb);
        float s16 = (lane < WW) ? cs0 : NINF;
        u32   p16 = (u32)(((1023u << 10) + 16u) + Mlow);
        kmaxf(TS[7], TP[7], s16, p16);
        BMERGE8P();          // T = local top-8 sorted desc

        // ---- 3.5: OVERLAP — softmax of frame t+1 + prefetch t+2 ----
        float lpn0, lpn1;
        {
            u32 mo = __reduce_max_sync(FULL, ord_of_float(fmaxf(nx0, nx1)));
            float mx = float_of_ord(mo);
            float e0 = expf(nx0 - mx);
            float e1 = (lane < 31) ? expf(nx1 - mx) : 0.0f;
            float sm = e0 + e1;
            #pragma unroll
            for (int off = 16; off; off >>= 1)
                sm += __shfl_xor_sync(FULL, sm, off);
            float lse = logf(sm);
            lpn0 = nx0 - mx - lse;
            lpn1 = nx1 - mx - lse;
        }
        {
            int tn = (t + 2 < TT) ? (t + 2) : (TT - 1);
            const float* nf = base + tn * CCC;
            nx0 = nf[lane];
            nx1 = (lane < 31) ? nf[lane + 32] : NINF;
        }

        // ---- 4: top-8 via REDUX head-pop (branchless) ----
        u32 sel_m = 0u, sel_lo = 0u;   // lane k holds pass-k winner
        #pragma unroll
        for (int k2 = 0; k2 < WW; ++k2) {
            u32 hi = ord_of_float(TS[0]);
            u32 m  = __reduce_max_sync(FULL, hi);
            u32 tx = (hi == m) ? TP[0] : 0u;
            u32 lw = __reduce_max_sync(FULL, tx);
            if (lane == k2) { sel_m = m; sel_lo = lw; }
            bool p = (lane == (int)((lw >> 5) & 31u));  // unique winner lane
            #pragma unroll
            for (int k = 0; k < 7; ++k) {
                TS[k] = p ? TS[k + 1] : TS[k];
                TP[k] = p ? TP[k + 1] : TP[k];
            }
            TS[7] = p ? NINF : TS[7];
            TP[7] = p ? 0u : TP[7];
        }

        // ---- 5: commit (gathers via shfl from OLD beam regs) ----
        int idx  = 1023 - (int)(sel_lo >> 10);
        bool stay = idx < WW;
        int slot = (int)(sel_lo & 31u);
        int wl   = (int)((sel_lo >> 5) & 31u);
        int src  = stay ? idx : (slot & 7);
        int c    = wl + ((slot & 8) ? 32 : 0);
        u32 g_h1   = __shfl_sync(FULL, bm_h1, src);
        u32 g_h2   = __shfl_sync(FULL, bm_h2, src);
        int g_last = __shfl_sync(FULL, bm_last, src);
        int g_len  = __shfl_sync(FULL, bm_len, src);
        float g_spb  = __shfl_sync(FULL, bm_spb, src);
        float g_mpnb = __shfl_sync(FULL, bm_mpnb, src);
        if (lane < WW) {
            bool alive = sel_m > ordDeadThr;
            float score = float_of_ord(sel_m);
            float npb  = stay ? g_spb  : NEGF;
            float npnb = stay ? g_mpnb : score;
            if (!alive) { npb = NEGF; npnb = NEGF; }
            bm_pb = npb; bm_pnb = npnb;
            bm_h1 = stay ? g_h1 : (g_h1 * HB1C + (u32)(c + 1));
            bm_h2 = stay ? g_h2 : (g_h2 * HB2C + (u32)(c + 1));
            bm_last = stay ? g_last : c;
            bm_len  = g_len + (stay ? 0 : 1);
            hist[wip][t * WW + lane] = stay
                ? (unsigned short)(idx << 8)
                : (unsigned short)(((slot & 7) << 8) | (c + 1));
        }
        lp0 = lpn0; lp1 = lpn1;
        dupmask = 0u;          // duplicates only possible at t=0
    }

    // ---- outputs: decoded [B*128], lengths [B], prob [B], all f32 ----
    float* dec = out + (size_t)b * TT;
    #pragma unroll
    for (int s2 = 0; s2 < 4; ++s2)
        dec[lane + 32 * s2] = -1.0f;
    __syncwarp();
    int len0 = __shfl_sync(FULL, bm_len, 0);
    float pb0  = __shfl_sync(FULL, bm_pb, 0);
    float pnb0 = __shfl_sync(FULL, bm_pnb, 0);
    if (lane == 0) {
        int cur = 0;
        int pos = len0 - 1;
        for (int tt = TT - 1; tt >= 0; --tt) {
            unsigned short h = hist[wip][tt * WW + cur];
            int cc = (int)(h & 0xFF) - 1;
            cur = h >> 8;
            if (cc >= 0) dec[pos--] = (float)cc;
        }
        out[(size_t)BATCH * TT + b] = (float)len0;
        out[(size_t)BATCH * TT + BATCH + b] = expf(lax_logaddexp(pb0, pnb0));
    }
}

extern "C" void kernel_launch(void* const* d_in, const int* in_sizes, int n_in,
                              void* d_out, int out_size) {
    const float* logits = (const float*)d_in[0];
    float* out = (float*)d_out;
    ctc_beam_kernel<<<BATCH / WPB, 32 * WPB>>>(logits, out);
}